// round 5
// baseline (speedup 1.0000x reference)
#include <cuda_runtime.h>
#include <cstdint>

// Problem geometry (fixed by setup_inputs: left/right are (1,3,320,960) f32).
#define H 320
#define W 960
#define HW (H * W)

// L2-resident scratch (static device globals -- no allocation allowed).
__device__ float g_yL[HW];
__device__ float g_yR[HW];
__device__ float g_cbL[HW];
__device__ float g_cbR[HW];
__device__ float g_crL[HW];
__device__ float g_crR[HW];
__device__ int   g_censL[HW];
__device__ int   g_censR[HW];

// ---------------------------------------------------------------------------
// Kernel 1: RGB -> YCbCr for both images.
// Y computed with explicit rn mul/add in the reference's left-to-right order
// (no FMA contraction) because census does exact >= comparisons on Y.
// ---------------------------------------------------------------------------
__global__ void ycbcr_kernel(const float* __restrict__ left,
                             const float* __restrict__ right) {
    int i = blockIdx.x * blockDim.x + threadIdx.x;
    if (i >= HW) return;

    {
        float r = left[i], g = left[i + HW], b = left[i + 2 * HW];
        float y = __fadd_rn(__fadd_rn(__fmul_rn(0.299f, r), __fmul_rn(0.587f, g)),
                            __fmul_rn(0.114f, b));
        g_yL[i]  = y;
        g_cbL[i] = (b - y) * 0.564f + 0.5f;
        g_crL[i] = (r - y) * 0.713f + 0.5f;
    }
    {
        float r = right[i], g = right[i + HW], b = right[i + 2 * HW];
        float y = __fadd_rn(__fadd_rn(__fmul_rn(0.299f, r), __fmul_rn(0.587f, g)),
                            __fmul_rn(0.114f, b));
        g_yR[i]  = y;
        g_cbR[i] = (b - y) * 0.564f + 0.5f;
        g_crR[i] = (r - y) * 0.713f + 0.5f;
    }
}

// ---------------------------------------------------------------------------
// Kernel 2: 5x5 census transform on Y (24 bits; loop skips (v==1 && u==1)
// exactly like the reference; includes the center (v==2,u==2) bit which is
// always 1). Border (2 px) is zero, matching jnp.pad.
// gridDim.y selects image: 0 = left, 1 = right.
// ---------------------------------------------------------------------------
__global__ void census_kernel() {
    int i = blockIdx.x * blockDim.x + threadIdx.x;
    if (i >= HW) return;
    const float* __restrict__ Y  = (blockIdx.y == 0) ? g_yL    : g_yR;
    int*         __restrict__ Cn = (blockIdx.y == 0) ? g_censL : g_censR;

    int y = i / W;
    int x = i - y * W;

    if (y < 2 || y >= H - 2 || x < 2 || x >= W - 2) {
        Cn[i] = 0;
        return;
    }
    float cy = Y[i];
    // Batch all 25 loads up front (high MLP), then compare.
    float s[25];
#pragma unroll
    for (int v = 0; v < 5; ++v) {
        const float* row = Y + (y - 2 + v) * W + (x - 2);
#pragma unroll
        for (int u = 0; u < 5; ++u)
            s[v * 5 + u] = row[u];
    }
    int code = 0;
#pragma unroll
    for (int v = 0; v < 5; ++v) {
#pragma unroll
        for (int u = 0; u < 5; ++u) {
            if (v == 1 && u == 1) continue;
            code = (code << 1) | (s[v * 5 + u] >= cy ? 1 : 0);
        }
    }
    Cn[i] = code;
}

// ---------------------------------------------------------------------------
// Kernel 3: cost volume. One block = one (d, y) row; thread t covers 4
// consecutive x (float4 stores to all three channel volumes).
// out layout: [3*D][H][W]; c1 = hamming, c2 = |dCb|, c3 = |dCr|.
// ---------------------------------------------------------------------------
__global__ void __launch_bounds__(240) volume_kernel(float* __restrict__ out, int D) {
    int g = threadIdx.x;                    // 0..239
    int y = blockIdx.y;
    int d = blockIdx.z;
    int x0 = g * 4;
    int base = y * W;

    // Right-image values: aligned vector loads.
    int4   c_r  = *reinterpret_cast<const int4*>  (g_censR + base + x0);
    float4 cb_r = *reinterpret_cast<const float4*>(g_cbR   + base + x0);
    float4 cr_r = *reinterpret_cast<const float4*>(g_crR   + base + x0);

    int   cri[4] = {c_r.x, c_r.y, c_r.z, c_r.w};
    float cbr[4] = {cb_r.x, cb_r.y, cb_r.z, cb_r.w};
    float crr[4] = {cr_r.x, cr_r.y, cr_r.z, cr_r.w};

    const int*   __restrict__ cL  = g_censL + base;
    const float* __restrict__ cbL = g_cbL   + base;
    const float* __restrict__ crL = g_crL   + base;

    float ham[4], dcb[4], dcr[4];
#pragma unroll
    for (int j = 0; j < 4; ++j) {
        int xs = x0 + j + d;
        if (xs < W) {
            ham[j] = (float)__popc(__ldg(cL + xs) ^ cri[j]);
            dcb[j] = fabsf(__ldg(cbL + xs) - cbr[j]);
            dcr[j] = fabsf(__ldg(crL + xs) - crr[j]);
        } else {
            ham[j] = 0.0f; dcb[j] = 0.0f; dcr[j] = 0.0f;
        }
    }

    size_t o1 = (size_t)d * HW + base + x0;
    size_t o2 = o1 + (size_t)D * HW;
    size_t o3 = o2 + (size_t)D * HW;
    *reinterpret_cast<float4*>(out + o1) = make_float4(ham[0], ham[1], ham[2], ham[3]);
    *reinterpret_cast<float4*>(out + o2) = make_float4(dcb[0], dcb[1], dcb[2], dcb[3]);
    *reinterpret_cast<float4*>(out + o3) = make_float4(dcr[0], dcr[1], dcr[2], dcr[3]);
}

// ---------------------------------------------------------------------------
extern "C" void kernel_launch(void* const* d_in, const int* in_sizes, int n_in,
                              void* d_out, int out_size) {
    const float* left  = (const float*)d_in[0];
    const float* right = (const float*)d_in[1];
    float* out = (float*)d_out;

    // maxdisp is a device scalar we can't read during capture; derive it
    // deterministically from the output size: out = (3*D, H, W).
    int D = out_size / (3 * HW);

    int threads = 256;
    int blocks  = (HW + threads - 1) / threads;

    ycbcr_kernel<<<blocks, threads>>>(left, right);

    dim3 cgrid(blocks, 2);
    census_kernel<<<cgrid, threads>>>();

    dim3 vgrid(1, H, D);
    volume_kernel<<<vgrid, 240>>>(out, D);
}

// round 7
// speedup vs baseline: 1.4074x; 1.4074x over previous
#include <cuda_runtime.h>
#include <cstdint>

// Problem geometry (fixed by setup_inputs: left/right are (1,3,320,960) f32).
#define H 320
#define W 960
#define HW (H * W)
#define PAD 128           // slack so widened left-window loads never run off the end
#define DCHUNK 8          // disparities per block in the volume kernel

// L2-resident scratch (static device globals -- no allocation allowed).
__device__ float g_yL[HW];
__device__ float g_yR[HW];
__device__ float g_cbL[HW + PAD];
__device__ float g_cbR[HW];
__device__ float g_crL[HW + PAD];
__device__ float g_crR[HW];
__device__ int   g_censL[HW + PAD];
__device__ int   g_censR[HW];

// ---------------------------------------------------------------------------
// Kernel 1: RGB -> YCbCr for both images.
// Y computed with explicit rn mul/add in the reference's left-to-right order
// (no FMA contraction) because census does exact >= comparisons on Y.
// ---------------------------------------------------------------------------
__global__ void ycbcr_kernel(const float* __restrict__ left,
                             const float* __restrict__ right) {
    int i = blockIdx.x * blockDim.x + threadIdx.x;
    if (i >= HW) return;

    {
        float r = left[i], g = left[i + HW], b = left[i + 2 * HW];
        float y = __fadd_rn(__fadd_rn(__fmul_rn(0.299f, r), __fmul_rn(0.587f, g)),
                            __fmul_rn(0.114f, b));
        g_yL[i]  = y;
        g_cbL[i] = (b - y) * 0.564f + 0.5f;
        g_crL[i] = (r - y) * 0.713f + 0.5f;
    }
    {
        float r = right[i], g = right[i + HW], b = right[i + 2 * HW];
        float y = __fadd_rn(__fadd_rn(__fmul_rn(0.299f, r), __fmul_rn(0.587f, g)),
                            __fmul_rn(0.114f, b));
        g_yR[i]  = y;
        g_cbR[i] = (b - y) * 0.564f + 0.5f;
        g_crR[i] = (r - y) * 0.713f + 0.5f;
    }
}

// ---------------------------------------------------------------------------
// Kernel 2: 5x5 census transform on Y (24 bits; loop skips (v==1 && u==1)
// exactly like the reference; includes the center (v==2,u==2) bit which is
// always 1). Border (2 px) is zero, matching jnp.pad.
// gridDim.y selects image: 0 = left, 1 = right.
// ---------------------------------------------------------------------------
__global__ void census_kernel() {
    int i = blockIdx.x * blockDim.x + threadIdx.x;
    if (i >= HW) return;
    const float* __restrict__ Y  = (blockIdx.y == 0) ? g_yL    : g_yR;
    int*         __restrict__ Cn = (blockIdx.y == 0) ? g_censL : g_censR;

    int y = i / W;
    int x = i - y * W;

    if (y < 2 || y >= H - 2 || x < 2 || x >= W - 2) {
        Cn[i] = 0;
        return;
    }
    float cy = Y[i];
    float s[25];
#pragma unroll
    for (int v = 0; v < 5; ++v) {
        const float* row = Y + (y - 2 + v) * W + (x - 2);
#pragma unroll
        for (int u = 0; u < 5; ++u)
            s[v * 5 + u] = row[u];
    }
    int code = 0;
#pragma unroll
    for (int v = 0; v < 5; ++v) {
#pragma unroll
        for (int u = 0; u < 5; ++u) {
            if (v == 1 && u == 1) continue;
            code = (code << 1) | (s[v * 5 + u] >= cy ? 1 : 0);
        }
    }
    Cn[i] = code;
}

// ---------------------------------------------------------------------------
// Kernel 3: cost volume, 8 disparities per block. Thread t covers x in
// [4t, 4t+4); block (y, d0..d0+7). Left windows for the 8 disparities span
// 11 contiguous elements per stream -> 3 aligned float4/int4 loads, shifted
// through registers. All stores are aligned float4 (full 128B lines/warp).
// out layout: [3*D][H][W]; c1 = hamming, c2 = |dCb|, c3 = |dCr|.
// ---------------------------------------------------------------------------
__global__ void __launch_bounds__(240) volume_kernel(float* __restrict__ out, int D) {
    int t  = threadIdx.x;                   // 0..239
    int y  = blockIdx.y;
    int d0 = blockIdx.z * DCHUNK;
    int x0 = t * 4;
    int base = y * W;

    // Right-image values: aligned vector loads (reused for all 8 disparities).
    int4   c_r  = *reinterpret_cast<const int4*>  (g_censR + base + x0);
    float4 cb_r = *reinterpret_cast<const float4*>(g_cbR   + base + x0);
    float4 cr_r = *reinterpret_cast<const float4*>(g_crR   + base + x0);

    int   cri[4] = {c_r.x, c_r.y, c_r.z, c_r.w};
    float cbr[4] = {cb_r.x, cb_r.y, cb_r.z, cb_r.w};
    float crr[4] = {cr_r.x, cr_r.y, cr_r.z, cr_r.w};

    // Left windows: positions [x0+d0, x0+d0+11). x0, d0 multiples of 4 ->
    // three aligned 16B loads per stream. PAD guarantees in-bounds; garbage
    // lanes are predicate-selected to 0 below (never fed into arithmetic).
    int gb = base + x0 + d0;
    float lcb[12], lcr[12];
    int   lcn[12];
    {
        float4 a0 = *reinterpret_cast<const float4*>(g_cbL + gb);
        float4 a1 = *reinterpret_cast<const float4*>(g_cbL + gb + 4);
        float4 a2 = *reinterpret_cast<const float4*>(g_cbL + gb + 8);
        lcb[0]=a0.x; lcb[1]=a0.y; lcb[2]=a0.z; lcb[3]=a0.w;
        lcb[4]=a1.x; lcb[5]=a1.y; lcb[6]=a1.z; lcb[7]=a1.w;
        lcb[8]=a2.x; lcb[9]=a2.y; lcb[10]=a2.z; lcb[11]=a2.w;
        float4 b0 = *reinterpret_cast<const float4*>(g_crL + gb);
        float4 b1 = *reinterpret_cast<const float4*>(g_crL + gb + 4);
        float4 b2 = *reinterpret_cast<const float4*>(g_crL + gb + 8);
        lcr[0]=b0.x; lcr[1]=b0.y; lcr[2]=b0.z; lcr[3]=b0.w;
        lcr[4]=b1.x; lcr[5]=b1.y; lcr[6]=b1.z; lcr[7]=b1.w;
        lcr[8]=b2.x; lcr[9]=b2.y; lcr[10]=b2.z; lcr[11]=b2.w;
        int4 c0 = *reinterpret_cast<const int4*>(g_censL + gb);
        int4 c1 = *reinterpret_cast<const int4*>(g_censL + gb + 4);
        int4 c2 = *reinterpret_cast<const int4*>(g_censL + gb + 8);
        lcn[0]=c0.x; lcn[1]=c0.y; lcn[2]=c0.z; lcn[3]=c0.w;
        lcn[4]=c1.x; lcn[5]=c1.y; lcn[6]=c1.z; lcn[7]=c1.w;
        lcn[8]=c2.x; lcn[9]=c2.y; lcn[10]=c2.z; lcn[11]=c2.w;
    }

#pragma unroll
    for (int dd = 0; dd < DCHUNK; ++dd) {
        int d = d0 + dd;
        if (d >= D) break;                  // D is always a multiple of 8 here
        float ham[4], dcb[4], dcr[4];
#pragma unroll
        for (int j = 0; j < 4; ++j) {
            bool valid = (x0 + d + j) < W;
            ham[j] = valid ? (float)__popc(lcn[dd + j] ^ cri[j]) : 0.0f;
            dcb[j] = valid ? fabsf(lcb[dd + j] - cbr[j]) : 0.0f;
            dcr[j] = valid ? fabsf(lcr[dd + j] - crr[j]) : 0.0f;
        }
        size_t o1 = (size_t)d * HW + base + x0;
        size_t o2 = o1 + (size_t)D * HW;
        size_t o3 = o2 + (size_t)D * HW;
        *reinterpret_cast<float4*>(out + o1) = make_float4(ham[0], ham[1], ham[2], ham[3]);
        *reinterpret_cast<float4*>(out + o2) = make_float4(dcb[0], dcb[1], dcb[2], dcb[3]);
        *reinterpret_cast<float4*>(out + o3) = make_float4(dcr[0], dcr[1], dcr[2], dcr[3]);
    }
}

// ---------------------------------------------------------------------------
extern "C" void kernel_launch(void* const* d_in, const int* in_sizes, int n_in,
                              void* d_out, int out_size) {
    const float* left  = (const float*)d_in[0];
    const float* right = (const float*)d_in[1];
    float* out = (float*)d_out;

    // maxdisp is a device scalar we can't read during capture; derive it
    // deterministically from the output size: out = (3*D, H, W).
    int D = out_size / (3 * HW);

    int threads = 256;
    int blocks  = (HW + threads - 1) / threads;

    ycbcr_kernel<<<blocks, threads>>>(left, right);

    dim3 cgrid(blocks, 2);
    census_kernel<<<cgrid, threads>>>();

    dim3 vgrid(1, H, (D + DCHUNK - 1) / DCHUNK);
    volume_kernel<<<vgrid, 240>>>(out, D);
}